// round 1
// baseline (speedup 1.0000x reference)
#include <cuda_runtime.h>

#define BSZ 512
#define FF  512
#define KK  32
#define DD  16
#define MCOLS (KK*DD)   // 512
#define OUTC  (FF+KK)   // 544

// scratch for m = x @ T  (1 MB, L2-resident)
__device__ float g_m[BSZ * MCOLS];

// ---------------------------------------------------------------------------
// Kernel 1: m = x @ T   (512x512x512 SGEMM, classic 32x32 shared tiling)
// grid (16,16), block (32,32)
// ---------------------------------------------------------------------------
__global__ void gemm_kernel(const float* __restrict__ x,
                            const float* __restrict__ T) {
    __shared__ float As[32][32];
    __shared__ float Bs[32][33];   // +1 pad: conflict-free column reads

    const int tx = threadIdx.x, ty = threadIdx.y;
    const int row = blockIdx.y * 32 + ty;
    const int col = blockIdx.x * 32 + tx;

    float acc = 0.f;
    for (int t = 0; t < FF; t += 32) {
        As[ty][tx] = x[row * FF + t + tx];
        Bs[ty][tx] = T[(t + ty) * MCOLS + col];
        __syncthreads();
#pragma unroll
        for (int kk = 0; kk < 32; kk++)
            acc += As[ty][kk] * Bs[kk][tx];
        __syncthreads();
    }
    g_m[row * MCOLS + col] = acc;
}

// ---------------------------------------------------------------------------
// Kernel 2: feats[i][k] = sum_j exp(-sum_d |m[i,k,d] - m[j,k,d]|)
// grid (B/128, K), block 128. Slice m[:,k,:] = 512x16 f32 = 32 KB in smem.
// j-loop is warp-uniform -> smem reads broadcast (no conflicts).
// ---------------------------------------------------------------------------
__global__ void feats_kernel(float* __restrict__ out) {
    const int k = blockIdx.y;
    const int i = blockIdx.x * 128 + threadIdx.x;

    __shared__ float sm[BSZ * DD];  // [j][d], 32 KB

    // cooperative load of the k-slice: 2048 float4's, 128 threads
    for (int idx = threadIdx.x; idx < BSZ * DD / 4; idx += 128) {
        const int j  = idx >> 2;       // DD/4 = 4 float4 per row
        const int d4 = idx & 3;
        float4 v = *(const float4*)&g_m[j * MCOLS + k * DD + d4 * 4];
        *(float4*)&sm[j * DD + d4 * 4] = v;
    }
    __syncthreads();

    float mi[DD];
#pragma unroll
    for (int d = 0; d < DD; d++) mi[d] = sm[i * DD + d];

    float acc = 0.f;
    for (int j = 0; j < BSZ; j++) {
        float dist = 0.f;
#pragma unroll
        for (int d = 0; d < DD; d++)
            dist += fabsf(mi[d] - sm[j * DD + d]);
        acc += __expf(-dist);
    }

    out[i * OUTC + FF + k] = acc;
}

// ---------------------------------------------------------------------------
// Kernel 3: out[:, :512] = x  (vectorized copy)
// ---------------------------------------------------------------------------
__global__ void copy_kernel(const float* __restrict__ x,
                            float* __restrict__ out) {
    const int idx = blockIdx.x * 256 + threadIdx.x;   // over B*F/4
    const int i = idx / (FF / 4);
    const int c = idx % (FF / 4);
    *(float4*)&out[i * OUTC + c * 4] = *(const float4*)&x[i * FF + c * 4];
}

// ---------------------------------------------------------------------------
extern "C" void kernel_launch(void* const* d_in, const int* in_sizes, int n_in,
                              void* d_out, int out_size) {
    const float* x = (const float*)d_in[0];
    const float* T = (const float*)d_in[1];
    float* out = (float*)d_out;

    dim3 gblk(32, 32), ggrd(MCOLS / 32, BSZ / 32);
    gemm_kernel<<<ggrd, gblk>>>(x, T);

    copy_kernel<<<(BSZ * FF / 4) / 256, 256>>>(x, out);

    dim3 fgrd(BSZ / 128, KK);
    feats_kernel<<<fgrd, 128>>>(out);
}

// round 3
// speedup vs baseline: 1.1416x; 1.1416x over previous
#include <cuda_runtime.h>

#define BSZ 512
#define FF  512
#define KK  32
#define DD  16
#define MCOLS (KK*DD)   // 512
#define OUTC  (FF+KK)   // 544

// split-K partial buffers for m = x @ T  (2 MB, L2-resident)
__device__ float g_part[2 * BSZ * MCOLS];

// ---------------------------------------------------------------------------
// Kernel 1: m_partial[z] = x[:, z*256:(z+1)*256] @ T[z*256:(z+1)*256, :]
// 64x64 CTA tile, BK=16, 256 threads, 4x4 micro-tile per thread.
// grid (8, 8, 2), block (16, 16)
// ---------------------------------------------------------------------------
__global__ void gemm_kernel(const float* __restrict__ x,
                            const float* __restrict__ T) {
    __shared__ __align__(16) float As[16][68];  // [k][m], pad to 68 (16B-aligned rows)
    __shared__ __align__(16) float Bs[16][64];  // [k][n]

    const int tx = threadIdx.x, ty = threadIdx.y;
    const int tid = ty * 16 + tx;
    const int m0 = blockIdx.y * 64;
    const int n0 = blockIdx.x * 64;
    const int koff = blockIdx.z * 256;

    // A load mapping: 256 float4 = 64 rows x 4 col-groups
    const int a_row = tid >> 2;
    const int a_c4  = (tid & 3) * 4;
    // B load mapping: 16 k-rows x 16 col-groups
    const int b_kr = tid >> 4;
    const int b_n4 = (tid & 15) * 4;

    float acc[4][4] = {};

    for (int kt = 0; kt < 256; kt += 16) {
        // load A tile (transposed into smem)
        float4 av = *(const float4*)&x[(m0 + a_row) * FF + koff + kt + a_c4];
        As[a_c4 + 0][a_row] = av.x;
        As[a_c4 + 1][a_row] = av.y;
        As[a_c4 + 2][a_row] = av.z;
        As[a_c4 + 3][a_row] = av.w;
        // load B tile
        *(float4*)&Bs[b_kr][b_n4] =
            *(const float4*)&T[(koff + kt + b_kr) * MCOLS + n0 + b_n4];
        __syncthreads();

#pragma unroll
        for (int kk = 0; kk < 16; kk++) {
            float4 a = *(const float4*)&As[kk][ty * 4];
            float4 b = *(const float4*)&Bs[kk][tx * 4];
            float ar[4] = {a.x, a.y, a.z, a.w};
            float br[4] = {b.x, b.y, b.z, b.w};
#pragma unroll
            for (int i = 0; i < 4; i++)
#pragma unroll
                for (int j = 0; j < 4; j++)
                    acc[i][j] += ar[i] * br[j];
        }
        __syncthreads();
    }

    float* dst = &g_part[blockIdx.z * BSZ * MCOLS];
#pragma unroll
    for (int i = 0; i < 4; i++) {
        float4 v = make_float4(acc[i][0], acc[i][1], acc[i][2], acc[i][3]);
        *(float4*)&dst[(m0 + ty * 4 + i) * MCOLS + n0 + tx * 4] = v;
    }
}

// ---------------------------------------------------------------------------
// Kernel 2: feats[i][k] = sum_j exp(-sum_d |m[i,k,d] - m[j,k,d]|)
// grid (B/128, K), block 256: threads [0,128) do j in [0,256),
// threads [128,256) do j in [256,512); smem combine.
// Slice m[:,k,:] summed from the two K-partials during load.
// ---------------------------------------------------------------------------
__global__ void feats_kernel(float* __restrict__ out) {
    const int k = blockIdx.y;
    const int half = threadIdx.x >> 7;          // 0 or 1
    const int li = threadIdx.x & 127;           // i-lane within block
    const int i = blockIdx.x * 128 + li;

    __shared__ float sm[BSZ * DD];              // [j][d], 32 KB
    __shared__ float spart[256];

    // cooperative load of k-slice, summing the two split-K partials
    for (int idx = threadIdx.x; idx < BSZ * DD / 4; idx += 256) {
        const int j  = idx >> 2;
        const int d4 = (idx & 3) * 4;
        const int g = j * MCOLS + k * DD + d4;
        float4 v0 = *(const float4*)&g_part[g];
        float4 v1 = *(const float4*)&g_part[BSZ * MCOLS + g];
        float4 v = make_float4(v0.x + v1.x, v0.y + v1.y, v0.z + v1.z, v0.w + v1.w);
        *(float4*)&sm[j * DD + d4] = v;
    }
    __syncthreads();

    float mi[DD];
#pragma unroll
    for (int d = 0; d < DD; d++) mi[d] = sm[i * DD + d];

    float acc = 0.f;
    const int j0 = half * 256;
    for (int j = j0; j < j0 + 256; j++) {
        float dist = 0.f;
#pragma unroll
        for (int d = 0; d < DD; d++)
            dist += fabsf(mi[d] - sm[j * DD + d]);
        acc += __expf(-dist);
    }

    spart[threadIdx.x] = acc;
    __syncthreads();
    if (threadIdx.x < 128)
        out[i * OUTC + FF + k] = spart[threadIdx.x] + spart[threadIdx.x + 128];
}

// ---------------------------------------------------------------------------
// Kernel 3: out[:, :512] = x  (vectorized copy)
// ---------------------------------------------------------------------------
__global__ void copy_kernel(const float* __restrict__ x,
                            float* __restrict__ out) {
    const int idx = blockIdx.x * 256 + threadIdx.x;   // over B*F/4
    const int i = idx / (FF / 4);
    const int c = idx % (FF / 4);
    *(float4*)&out[i * OUTC + c * 4] = *(const float4*)&x[i * FF + c * 4];
}

// ---------------------------------------------------------------------------
extern "C" void kernel_launch(void* const* d_in, const int* in_sizes, int n_in,
                              void* d_out, int out_size) {
    const float* x = (const float*)d_in[0];
    const float* T = (const float*)d_in[1];
    float* out = (float*)d_out;

    dim3 gblk(16, 16), ggrd(8, 8, 2);
    gemm_kernel<<<ggrd, gblk>>>(x, T);

    copy_kernel<<<(BSZ * FF / 4) / 256, 256>>>(x, out);

    dim3 fgrd(BSZ / 128, KK);
    feats_kernel<<<fgrd, 256>>>(out);
}

// round 4
// speedup vs baseline: 1.4364x; 1.2582x over previous
#include <cuda_runtime.h>

#define BSZ 512
#define FF  512
#define KK  32
#define DD  16
#define MCOLS (KK*DD)   // 512
#define OUTC  (FF+KK)   // 544
#define SPLITK 8

typedef unsigned long long u64;

// split-K partial buffers for m = x @ T  (8 MB, L2-resident)
__device__ float g_part[SPLITK * BSZ * MCOLS];

// packed f32x2 helpers (sm_103a; ptxas only emits FFMA2 via PTX f32x2)
#define FMA2(acc, a, b) asm("fma.rn.f32x2 %0, %1, %2, %0;" : "+l"(acc) : "l"(a), "l"(b))
#define ADD2(d, a, b)   asm("add.rn.f32x2 %0, %1, %2;"     : "=l"(d)   : "l"(a), "l"(b))
#define PACK2(d, lo, hi) asm("mov.b64 %0, {%1, %2};" : "=l"(d) : "f"(lo), "f"(hi))
#define UNPACK2(lo, hi, s) asm("mov.b64 {%0, %1}, %2;" : "=f"(lo), "=f"(hi) : "l"(s))

// ---------------------------------------------------------------------------
// Kernel 1: split-K SGEMM, 128x128 CTA tile, 8x8 micro-tile, FFMA2.
// grid (4, 4, 8), block 256.  Each CTA: K-chunk of 64, BK=16.
// ---------------------------------------------------------------------------
__global__ __launch_bounds__(256, 1)
void gemm_kernel(const float* __restrict__ x, const float* __restrict__ T) {
    __shared__ __align__(16) float As[16][132];  // [k][m], 528B rows (16B-aligned)
    __shared__ __align__(16) float Bs[16][128];  // [k][n]

    const int tid = threadIdx.x;
    const int tx = tid & 15, ty = tid >> 4;
    const int m0 = blockIdx.y * 128, n0 = blockIdx.x * 128;
    const int koff = blockIdx.z * 64;

    u64 acc[8][4];
#pragma unroll
    for (int i = 0; i < 8; i++)
#pragma unroll
        for (int j = 0; j < 4; j++) acc[i][j] = 0ull;  // (+0.f, +0.f)

    for (int kt = 0; kt < 64; kt += 16) {
        // A tile: 128 rows x 16 k, transposed into As (512 float4, 2/thread)
#pragma unroll
        for (int s = 0; s < 2; s++) {
            int q = tid + 256 * s;
            int row = q >> 2, c4 = (q & 3) * 4;
            float4 av = *(const float4*)&x[(m0 + row) * FF + koff + kt + c4];
            As[c4 + 0][row] = av.x;
            As[c4 + 1][row] = av.y;
            As[c4 + 2][row] = av.z;
            As[c4 + 3][row] = av.w;
        }
        // B tile: 16 k-rows x 128 n (512 float4, 2/thread)
#pragma unroll
        for (int s = 0; s < 2; s++) {
            int q = tid + 256 * s;
            int kr = q >> 5, nc = (q & 31) * 4;
            *(float4*)&Bs[kr][nc] =
                *(const float4*)&T[(koff + kt + kr) * MCOLS + n0 + nc];
        }
        __syncthreads();

#pragma unroll
        for (int kk = 0; kk < 16; kk++) {
            float4 a0 = *(const float4*)&As[kk][ty * 8];
            float4 a1 = *(const float4*)&As[kk][ty * 8 + 4];
            float4 b0 = *(const float4*)&Bs[kk][tx * 8];
            float4 b1 = *(const float4*)&Bs[kk][tx * 8 + 4];
            u64 bp[4], ap[8];
            PACK2(bp[0], b0.x, b0.y);
            PACK2(bp[1], b0.z, b0.w);
            PACK2(bp[2], b1.x, b1.y);
            PACK2(bp[3], b1.z, b1.w);
            float ar[8] = {a0.x, a0.y, a0.z, a0.w, a1.x, a1.y, a1.z, a1.w};
#pragma unroll
            for (int i = 0; i < 8; i++) PACK2(ap[i], ar[i], ar[i]);
#pragma unroll
            for (int i = 0; i < 8; i++)
#pragma unroll
                for (int j = 0; j < 4; j++)
                    FMA2(acc[i][j], ap[i], bp[j]);
        }
        __syncthreads();
    }

    float* dst = &g_part[blockIdx.z * BSZ * MCOLS];
#pragma unroll
    for (int i = 0; i < 8; i++) {
        float v[8];
#pragma unroll
        for (int j = 0; j < 4; j++) UNPACK2(v[2 * j], v[2 * j + 1], acc[i][j]);
        float4 lo = make_float4(v[0], v[1], v[2], v[3]);
        float4 hi = make_float4(v[4], v[5], v[6], v[7]);
        float* r = &dst[(m0 + ty * 8 + i) * MCOLS + n0 + tx * 8];
        *(float4*)&r[0] = lo;
        *(float4*)&r[4] = hi;
    }
}

// ---------------------------------------------------------------------------
// Kernel 2: feats[i][k] = sum_j exp(-sum_d |m[i,k,d] - m[j,k,d]|)
// grid (4, 32), block 256 (two j-halves x 128 i-lanes), smem combine.
// Slice stored NEGATED so diff = add.f32x2; abs via 64-bit AND (alu pipe).
// Split-K partials summed during the slice load.
// ---------------------------------------------------------------------------
__global__ __launch_bounds__(256)
void feats_kernel(float* __restrict__ out) {
    const int k = blockIdx.y;
    const int half = threadIdx.x >> 7;
    const int li = threadIdx.x & 127;
    const int i = blockIdx.x * 128 + li;

    __shared__ __align__(16) float sneg[BSZ * DD];  // -(m slice), 32 KB
    __shared__ float spart[256];

    for (int idx = threadIdx.x; idx < BSZ * DD / 4; idx += 256) {
        const int j = idx >> 2;
        const int d4 = (idx & 3) * 4;
        const int g = j * MCOLS + k * DD + d4;
        float4 a = make_float4(0.f, 0.f, 0.f, 0.f);
#pragma unroll
        for (int z = 0; z < SPLITK; z++) {
            float4 v = *(const float4*)&g_part[z * BSZ * MCOLS + g];
            a.x += v.x; a.y += v.y; a.z += v.z; a.w += v.w;
        }
        *(float4*)&sneg[j * DD + d4] = make_float4(-a.x, -a.y, -a.z, -a.w);
    }
    __syncthreads();

    u64 mi2[8];
#pragma unroll
    for (int p = 0; p < 8; p++) {
        float lo = -sneg[i * DD + 2 * p];
        float hi = -sneg[i * DD + 2 * p + 1];
        PACK2(mi2[p], lo, hi);
    }

    const u64 ABSM = 0x7FFFFFFF7FFFFFFFull;
    float acc = 0.f;
    const int j0 = half * 256;
#pragma unroll 2
    for (int j = j0; j < j0 + 256; j++) {
        const ulonglong2* row = (const ulonglong2*)&sneg[j * DD];
        u64 s0 = 0ull, s1 = 0ull;
#pragma unroll
        for (int p = 0; p < 4; p++) {
            ulonglong2 rp = row[p];
            u64 d0, d1;
            ADD2(d0, mi2[2 * p], rp.x);
            ADD2(d1, mi2[2 * p + 1], rp.y);
            d0 &= ABSM;
            d1 &= ABSM;
            ADD2(s0, s0, d0);
            ADD2(s1, s1, d1);
        }
        ADD2(s0, s0, s1);
        float lo, hi;
        UNPACK2(lo, hi, s0);
        acc += __expf(-(lo + hi));
    }

    spart[threadIdx.x] = acc;
    __syncthreads();
    if (threadIdx.x < 128)
        out[i * OUTC + FF + k] = spart[threadIdx.x] + spart[threadIdx.x + 128];
}

// ---------------------------------------------------------------------------
// Kernel 3: out[:, :512] = x  (vectorized copy)
// ---------------------------------------------------------------------------
__global__ void copy_kernel(const float* __restrict__ x,
                            float* __restrict__ out) {
    const int idx = blockIdx.x * 256 + threadIdx.x;   // over B*F/4
    const int i = idx / (FF / 4);
    const int c = idx % (FF / 4);
    *(float4*)&out[i * OUTC + c * 4] = *(const float4*)&x[i * FF + c * 4];
}

// ---------------------------------------------------------------------------
extern "C" void kernel_launch(void* const* d_in, const int* in_sizes, int n_in,
                              void* d_out, int out_size) {
    const float* x = (const float*)d_in[0];
    const float* T = (const float*)d_in[1];
    float* out = (float*)d_out;

    dim3 ggrd(4, 4, SPLITK);
    gemm_kernel<<<ggrd, 256>>>(x, T);

    copy_kernel<<<(BSZ * FF / 4) / 256, 256>>>(x, out);

    dim3 fgrd(4, KK);
    feats_kernel<<<fgrd, 256>>>(out);
}

// round 5
// speedup vs baseline: 1.5367x; 1.0698x over previous
#include <cuda_runtime.h>

#define BSZ 512
#define FF  512
#define KK  32
#define DD  16
#define MCOLS 512
#define OUTC  544
#define SPLITK 8

typedef unsigned long long u64;

// split-K partials (8 MB) + reduced negated m (1 MB), both L2-resident
__device__ float g_part[SPLITK * BSZ * MCOLS];
__device__ float g_negm[BSZ * MCOLS];

// packed f32x2 helpers (FFMA2/FADD2 only reachable via PTX f32x2)
#define FMA2(acc, a, b)  asm("fma.rn.f32x2 %0, %1, %2, %0;" : "+l"(acc) : "l"(a), "l"(b))
#define ADD2(d, a, b)    asm("add.rn.f32x2 %0, %1, %2;"     : "=l"(d)   : "l"(a), "l"(b))
#define PACK2(d, lo, hi) asm("mov.b64 %0, {%1, %2};"  : "=l"(d) : "f"(lo), "f"(hi))
#define UNPACK2(lo, hi, s) asm("mov.b64 {%0, %1}, %2;" : "=f"(lo), "=f"(hi) : "l"(s))

// ---------------------------------------------------------------------------
// Kernel 1: split-K SGEMM. 128x128 tile, 512 threads, 4x8 micro-tile, FFMA2.
// A kept DUPLICATED in smem as u64 pairs -> mainloop has zero pack-MOVs.
// Double-buffered smem, one barrier per kt. grid (4,4,8).
// ---------------------------------------------------------------------------
__global__ __launch_bounds__(512, 1)
void gemm_kernel(const float* __restrict__ x, const float* __restrict__ T) {
    __shared__ __align__(16) u64   As[2][16][128];  // [buf][k][m] dup pairs, 32 KB
    __shared__ __align__(16) float Bs[2][16][128];  // [buf][k][n], 16 KB

    const int tid = threadIdx.x;
    const int tx = tid & 15;    // n block: tx*8
    const int ty = tid >> 4;    // m block: ty*4
    const int m0 = blockIdx.y * 128, n0 = blockIdx.x * 128;
    const int koff = blockIdx.z * 64;

    const int a_row = tid >> 2;         // 128 rows
    const int a_c4  = (tid & 3) * 4;    // 4 k-groups of 4
    const int b_kr  = tid >> 5;         // 16 k-rows
    const int b_nc  = (tid & 31) * 4;   // 32 n-groups of 4

    u64 acc[4][4];
#pragma unroll
    for (int i = 0; i < 4; i++)
#pragma unroll
        for (int j = 0; j < 4; j++) acc[i][j] = 0ull;

    // prologue: stage kt=0 into buf 0
    {
        float4 av = *(const float4*)&x[(m0 + a_row) * FF + koff + a_c4];
        u64 d;
        PACK2(d, av.x, av.x); As[0][a_c4 + 0][a_row] = d;
        PACK2(d, av.y, av.y); As[0][a_c4 + 1][a_row] = d;
        PACK2(d, av.z, av.z); As[0][a_c4 + 2][a_row] = d;
        PACK2(d, av.w, av.w); As[0][a_c4 + 3][a_row] = d;
        *(float4*)&Bs[0][b_kr][b_nc] =
            *(const float4*)&T[(koff + b_kr) * MCOLS + n0 + b_nc];
    }
    __syncthreads();

#pragma unroll
    for (int kt = 0; kt < 64; kt += 16) {
        const int buf = (kt >> 4) & 1;
        float4 av, bv;
        const bool has_next = (kt + 16) < 64;
        if (has_next) {   // prefetch next tile into regs
            av = *(const float4*)&x[(m0 + a_row) * FF + koff + kt + 16 + a_c4];
            bv = *(const float4*)&T[(koff + kt + 16 + b_kr) * MCOLS + n0 + b_nc];
        }

#pragma unroll
        for (int kk = 0; kk < 16; kk++) {
            ulonglong2 a01 = *(const ulonglong2*)&As[buf][kk][ty * 4];
            ulonglong2 a23 = *(const ulonglong2*)&As[buf][kk][ty * 4 + 2];
            ulonglong2 b01 = *(const ulonglong2*)&Bs[buf][kk][tx * 8];
            ulonglong2 b23 = *(const ulonglong2*)&Bs[buf][kk][tx * 8 + 4];
            u64 a2[4] = {a01.x, a01.y, a23.x, a23.y};
            u64 bp[4] = {b01.x, b01.y, b23.x, b23.y};
#pragma unroll
            for (int i = 0; i < 4; i++)
#pragma unroll
                for (int j = 0; j < 4; j++)
                    FMA2(acc[i][j], a2[i], bp[j]);
        }

        if (has_next) {
            const int nb = buf ^ 1;
            u64 d;
            PACK2(d, av.x, av.x); As[nb][a_c4 + 0][a_row] = d;
            PACK2(d, av.y, av.y); As[nb][a_c4 + 1][a_row] = d;
            PACK2(d, av.z, av.z); As[nb][a_c4 + 2][a_row] = d;
            PACK2(d, av.w, av.w); As[nb][a_c4 + 3][a_row] = d;
            *(float4*)&Bs[nb][b_kr][b_nc] = bv;
            __syncthreads();
        }
    }

    float* dst = &g_part[blockIdx.z * (BSZ * MCOLS)];
#pragma unroll
    for (int i = 0; i < 4; i++) {
        float v[8];
#pragma unroll
        for (int j = 0; j < 4; j++) UNPACK2(v[2 * j], v[2 * j + 1], acc[i][j]);
        float* r = &dst[(m0 + ty * 4 + i) * MCOLS + n0 + tx * 8];
        *(float4*)&r[0] = make_float4(v[0], v[1], v[2], v[3]);
        *(float4*)&r[4] = make_float4(v[4], v[5], v[6], v[7]);
    }
}

// ---------------------------------------------------------------------------
// Kernel 2: fused (a) reduce split-K partials -> g_negm = -(sum partials)
//           (b) out[:, :512] = x
// grid 512: blocks [0,256) reduce, [256,512) copy. block 256.
// ---------------------------------------------------------------------------
__global__ __launch_bounds__(256)
void reduce_copy_kernel(const float* __restrict__ x, float* __restrict__ out) {
    if (blockIdx.x < 256) {
        const int e = (blockIdx.x * 256 + threadIdx.x) * 4;  // 256K floats
        float4 a = make_float4(0.f, 0.f, 0.f, 0.f);
#pragma unroll
        for (int z = 0; z < SPLITK; z++) {
            float4 v = *(const float4*)&g_part[z * (BSZ * MCOLS) + e];
            a.x += v.x; a.y += v.y; a.z += v.z; a.w += v.w;
        }
        *(float4*)&g_negm[e] = make_float4(-a.x, -a.y, -a.z, -a.w);
    } else {
        const int idx = (blockIdx.x - 256) * 256 + threadIdx.x;  // over B*F/4
        const int i = idx / (FF / 4);
        const int c = idx % (FF / 4);
        *(float4*)&out[i * OUTC + c * 4] = *(const float4*)&x[i * FF + c * 4];
    }
}

// ---------------------------------------------------------------------------
// Kernel 3: feats[i][k] = sum_j exp(-sum_d |m[i,k,d] - m[j,k,d]|)
// grid (16, 32) = 512 CTAs, block 256 = 32 i-lanes x 8 j-splits (64 j each).
// Slice in smem is NEGATED -> diff = packed add; abs via 64-bit AND (alu pipe).
// ---------------------------------------------------------------------------
__global__ __launch_bounds__(256)
void feats_kernel(float* __restrict__ out) {
    const int k  = blockIdx.y;
    const int it = blockIdx.x;
    const int li = threadIdx.x & 31;
    const int js = threadIdx.x >> 5;
    const int i  = it * 32 + li;

    __shared__ __align__(16) float sneg[BSZ * DD];  // -(m slice), 32 KB
    __shared__ float spart[8][32];

    for (int idx = threadIdx.x; idx < BSZ * DD / 4; idx += 256) {
        const int j = idx >> 2;
        const int d4 = (idx & 3) * 4;
        *(float4*)&sneg[j * DD + d4] =
            *(const float4*)&g_negm[j * MCOLS + k * DD + d4];
    }
    __syncthreads();

    // m_i (positive) straight from gmem — avoids a strided smem gather
    u64 mi2[8];
#pragma unroll
    for (int p = 0; p < 4; p++) {
        float4 v = *(const float4*)&g_negm[i * MCOLS + k * DD + p * 4];
        PACK2(mi2[2 * p + 0], -v.x, -v.y);
        PACK2(mi2[2 * p + 1], -v.z, -v.w);
    }

    const u64 ABSM = 0x7FFFFFFF7FFFFFFFull;
    float acc = 0.f;
    const int j0 = js * 64;
#pragma unroll 2
    for (int j = j0; j < j0 + 64; j++) {
        const ulonglong2* row = (const ulonglong2*)&sneg[j * DD];
        u64 s0 = 0ull, s1 = 0ull;
#pragma unroll
        for (int p = 0; p < 4; p++) {
            ulonglong2 rp = row[p];
            u64 d0, d1;
            ADD2(d0, mi2[2 * p], rp.x);
            ADD2(d1, mi2[2 * p + 1], rp.y);
            d0 &= ABSM;
            d1 &= ABSM;
            ADD2(s0, s0, d0);
            ADD2(s1, s1, d1);
        }
        ADD2(s0, s0, s1);
        float lo, hi;
        UNPACK2(lo, hi, s0);
        acc += __expf(-(lo + hi));
    }

    spart[js][li] = acc;
    __syncthreads();
    if (threadIdx.x < 32) {
        float s = 0.f;
#pragma unroll
        for (int q = 0; q < 8; q++) s += spart[q][threadIdx.x];
        out[(it * 32 + threadIdx.x) * OUTC + FF + k] = s;
    }
}

// ---------------------------------------------------------------------------
extern "C" void kernel_launch(void* const* d_in, const int* in_sizes, int n_in,
                              void* d_out, int out_size) {
    const float* x = (const float*)d_in[0];
    const float* T = (const float*)d_in[1];
    float* out = (float*)d_out;

    dim3 ggrd(4, 4, SPLITK);
    gemm_kernel<<<ggrd, 512>>>(x, T);

    reduce_copy_kernel<<<512, 256>>>(x, out);

    dim3 fgrd(16, KK);
    feats_kernel<<<fgrd, 256>>>(out);
}

// round 6
// speedup vs baseline: 1.5741x; 1.0243x over previous
#include <cuda_runtime.h>

#define BSZ 512
#define FF  512
#define KK  32
#define DD  16
#define MCOLS 512
#define OUTC  544
#define SPLITK 16

typedef unsigned long long u64;

// split-K partials (16 MB) + reduced negated m (1 MB), L2-resident
__device__ float g_part[SPLITK * BSZ * MCOLS];
__device__ float g_negm[BSZ * MCOLS];

// packed f32x2 helpers (FFMA2/FADD2 only reachable via PTX f32x2)
#define FMA2(acc, a, b)  asm("fma.rn.f32x2 %0, %1, %2, %0;" : "+l"(acc) : "l"(a), "l"(b))
#define ADD2(d, a, b)    asm("add.rn.f32x2 %0, %1, %2;"     : "=l"(d)   : "l"(a), "l"(b))
#define PACK2(d, lo, hi) asm("mov.b64 %0, {%1, %2};"  : "=l"(d) : "f"(lo), "f"(hi))
#define UNPACK2(lo, hi, s) asm("mov.b64 {%0, %1}, %2;" : "=f"(lo), "=f"(hi) : "l"(s))

// ---------------------------------------------------------------------------
// Kernel 1: split-K SGEMM. 128x128 CTA tile, 256 threads, 8x8 micro-tile.
// A duplicated in smem as u64 pairs; B plain. BK=8, double-buffered.
// grid (4,4,16) = 256 CTAs -> 2 CTAs/SM, 4 warps/SMSP.
// ---------------------------------------------------------------------------
__global__ __launch_bounds__(256, 2)
void gemm_kernel(const float* __restrict__ x, const float* __restrict__ T) {
    __shared__ __align__(16) u64   As[2][8][128];  // [buf][k][m] dup pairs, 8 KB/buf
    __shared__ __align__(16) float Bs[2][8][128];  // [buf][k][n], 4 KB/buf

    const int tid = threadIdx.x;
    const int tx = tid & 15;    // n: tx*8
    const int ty = tid >> 4;    // m: ty*8
    const int m0 = blockIdx.y * 128, n0 = blockIdx.x * 128;
    const int koff = blockIdx.z * 32;   // K-chunk = 32

    // A load: 128 rows x 2 k-groups of 4 -> 256 float4
    const int a_row = tid >> 1;
    const int a_k4  = (tid & 1) * 4;
    // B load: 8 k-rows x 32 n-groups of 4 -> 256 float4
    const int b_kr  = tid >> 5;
    const int b_nc  = (tid & 31) * 4;

    u64 acc[8][4];
#pragma unroll
    for (int i = 0; i < 8; i++)
#pragma unroll
        for (int j = 0; j < 4; j++) acc[i][j] = 0ull;

    // prologue: stage kt=0 into buf 0
    {
        float4 av = *(const float4*)&x[(m0 + a_row) * FF + koff + a_k4];
        u64 d;
        PACK2(d, av.x, av.x); As[0][a_k4 + 0][a_row] = d;
        PACK2(d, av.y, av.y); As[0][a_k4 + 1][a_row] = d;
        PACK2(d, av.z, av.z); As[0][a_k4 + 2][a_row] = d;
        PACK2(d, av.w, av.w); As[0][a_k4 + 3][a_row] = d;
        *(float4*)&Bs[0][b_kr][b_nc] =
            *(const float4*)&T[(koff + b_kr) * MCOLS + n0 + b_nc];
    }
    __syncthreads();

#pragma unroll
    for (int kt = 0; kt < 32; kt += 8) {
        const int buf = (kt >> 3) & 1;
        const bool has_next = (kt + 8) < 32;
        float4 av, bv;
        if (has_next) {
            av = *(const float4*)&x[(m0 + a_row) * FF + koff + kt + 8 + a_k4];
            bv = *(const float4*)&T[(koff + kt + 8 + b_kr) * MCOLS + n0 + b_nc];
        }

#pragma unroll
        for (int kk = 0; kk < 8; kk++) {
            ulonglong2 a01 = *(const ulonglong2*)&As[buf][kk][ty * 8];
            ulonglong2 a23 = *(const ulonglong2*)&As[buf][kk][ty * 8 + 2];
            ulonglong2 a45 = *(const ulonglong2*)&As[buf][kk][ty * 8 + 4];
            ulonglong2 a67 = *(const ulonglong2*)&As[buf][kk][ty * 8 + 6];
            ulonglong2 b01 = *(const ulonglong2*)&Bs[buf][kk][tx * 8];
            ulonglong2 b23 = *(const ulonglong2*)&Bs[buf][kk][tx * 8 + 4];
            u64 ap[8] = {a01.x, a01.y, a23.x, a23.y, a45.x, a45.y, a67.x, a67.y};
            u64 bp[4] = {b01.x, b01.y, b23.x, b23.y};
#pragma unroll
            for (int i = 0; i < 8; i++)
#pragma unroll
                for (int j = 0; j < 4; j++)
                    FMA2(acc[i][j], ap[i], bp[j]);
        }

        if (has_next) {
            const int nb = buf ^ 1;
            u64 d;
            PACK2(d, av.x, av.x); As[nb][a_k4 + 0][a_row] = d;
            PACK2(d, av.y, av.y); As[nb][a_k4 + 1][a_row] = d;
            PACK2(d, av.z, av.z); As[nb][a_k4 + 2][a_row] = d;
            PACK2(d, av.w, av.w); As[nb][a_k4 + 3][a_row] = d;
            *(float4*)&Bs[nb][b_kr][b_nc] = bv;
            __syncthreads();
        }
    }

    float* dst = &g_part[blockIdx.z * (BSZ * MCOLS)];
#pragma unroll
    for (int i = 0; i < 8; i++) {
        float v[8];
#pragma unroll
        for (int j = 0; j < 4; j++) UNPACK2(v[2 * j], v[2 * j + 1], acc[i][j]);
        float* r = &dst[(m0 + ty * 8 + i) * MCOLS + n0 + tx * 8];
        *(float4*)&r[0] = make_float4(v[0], v[1], v[2], v[3]);
        *(float4*)&r[4] = make_float4(v[4], v[5], v[6], v[7]);
    }
}

// ---------------------------------------------------------------------------
// Kernel 2: fused (a) g_negm = -(sum of SPLITK partials)  (b) out[:, :512] = x
// grid 512: blocks [0,256) reduce, [256,512) copy. block 256.
// ---------------------------------------------------------------------------
__global__ __launch_bounds__(256)
void reduce_copy_kernel(const float* __restrict__ x, float* __restrict__ out) {
    if (blockIdx.x < 256) {
        const int e = (blockIdx.x * 256 + threadIdx.x) * 4;
        float4 a = make_float4(0.f, 0.f, 0.f, 0.f);
#pragma unroll
        for (int z = 0; z < SPLITK; z++) {
            float4 v = *(const float4*)&g_part[z * (BSZ * MCOLS) + e];
            a.x += v.x; a.y += v.y; a.z += v.z; a.w += v.w;
        }
        *(float4*)&g_negm[e] = make_float4(-a.x, -a.y, -a.z, -a.w);
    } else {
        const int idx = (blockIdx.x - 256) * 256 + threadIdx.x;
        const int i = idx / (FF / 4);
        const int c = idx % (FF / 4);
        *(float4*)&out[i * OUTC + c * 4] = *(const float4*)&x[i * FF + c * 4];
    }
}

// ---------------------------------------------------------------------------
// Kernel 3: feats[i][k] = sum_j exp(-sum_d |m[i,k,d] - m[j,k,d]|)
// grid (16, 32), block 256 = 32 i-lanes x 8 j-splits (64 j each).
// Slice in smem is NEGATED -> diff = packed add; abs via 64-bit AND (alu pipe).
// ---------------------------------------------------------------------------
__global__ __launch_bounds__(256)
void feats_kernel(float* __restrict__ out) {
    const int k  = blockIdx.y;
    const int it = blockIdx.x;
    const int li = threadIdx.x & 31;
    const int js = threadIdx.x >> 5;
    const int i  = it * 32 + li;

    __shared__ __align__(16) float sneg[BSZ * DD];  // 32 KB
    __shared__ float spart[8][32];

    for (int idx = threadIdx.x; idx < BSZ * DD / 4; idx += 256) {
        const int j = idx >> 2;
        const int d4 = (idx & 3) * 4;
        *(float4*)&sneg[j * DD + d4] =
            *(const float4*)&g_negm[j * MCOLS + k * DD + d4];
    }
    __syncthreads();

    u64 mi2[8];
#pragma unroll
    for (int p = 0; p < 4; p++) {
        float4 v = *(const float4*)&g_negm[i * MCOLS + k * DD + p * 4];
        PACK2(mi2[2 * p + 0], -v.x, -v.y);
        PACK2(mi2[2 * p + 1], -v.z, -v.w);
    }

    const u64 ABSM = 0x7FFFFFFF7FFFFFFFull;
    float acc = 0.f;
    const int j0 = js * 64;
#pragma unroll 2
    for (int j = j0; j < j0 + 64; j++) {
        const ulonglong2* row = (const ulonglong2*)&sneg[j * DD];
        u64 s0 = 0ull, s1 = 0ull;
#pragma unroll
        for (int p = 0; p < 4; p++) {
            ulonglong2 rp = row[p];
            u64 d0, d1;
            ADD2(d0, mi2[2 * p], rp.x);
            ADD2(d1, mi2[2 * p + 1], rp.y);
            d0 &= ABSM;
            d1 &= ABSM;
            ADD2(s0, s0, d0);
            ADD2(s1, s1, d1);
        }
        ADD2(s0, s0, s1);
        float lo, hi;
        UNPACK2(lo, hi, s0);
        acc += __expf(-(lo + hi));
    }

    spart[js][li] = acc;
    __syncthreads();
    if (threadIdx.x < 32) {
        float s = 0.f;
#pragma unroll
        for (int q = 0; q < 8; q++) s += spart[q][threadIdx.x];
        out[(it * 32 + threadIdx.x) * OUTC + FF + k] = s;
    }
}

// ---------------------------------------------------------------------------
extern "C" void kernel_launch(void* const* d_in, const int* in_sizes, int n_in,
                              void* d_out, int out_size) {
    const float* x = (const float*)d_in[0];
    const float* T = (const float*)d_in[1];
    float* out = (float*)d_out;

    dim3 ggrd(4, 4, SPLITK);
    gemm_kernel<<<ggrd, 256>>>(x, T);

    reduce_copy_kernel<<<512, 256>>>(x, out);

    dim3 fgrd(16, KK);
    feats_kernel<<<fgrd, 256>>>(out);
}

// round 9
// speedup vs baseline: 2.0538x; 1.3048x over previous
#include <cuda_runtime.h>
#include <cstdint>

#define BSZ 512
#define FF  512
#define KK  32
#define DD  16
#define MCOLS 512
#define OUTC  544
#define SPLITK 4

typedef unsigned long long u64;
typedef unsigned int u32;

// split-K partials (4 MB) + reduced negated m (1 MB), L2-resident
__device__ float g_part[SPLITK * BSZ * MCOLS];
__device__ float g_negm[BSZ * MCOLS];

// ---------------- packed f32x2 helpers (for feats) ----------------
#define ADD2(d, a, b)    asm("add.rn.f32x2 %0, %1, %2;" : "=l"(d) : "l"(a), "l"(b))
#define PACK2(d, lo, hi) asm("mov.b64 %0, {%1, %2};"  : "=l"(d) : "f"(lo), "f"(hi))
#define UNPACK2(lo, hi, s) asm("mov.b64 {%0, %1}, %2;" : "=f"(lo), "=f"(hi) : "l"(s))

// ---------------- tf32 mma.sync helpers (sm_80+, works on compute_103) ----------------
__device__ __forceinline__ u32 f2tf32(float f) {
    u32 o;
    asm("cvt.rna.tf32.f32 %0, %1;" : "=r"(o) : "f"(f));
    return o;
}
#define MMA_TF32(d0, d1, d2, d3, a0, a1, a2, a3, b0, b1) \
    asm volatile("mma.sync.aligned.m16n8k8.row.col.f32.tf32.tf32.f32 " \
                 "{%0,%1,%2,%3}, {%4,%5,%6,%7}, {%8,%9}, {%0,%1,%2,%3};" \
                 : "+f"(d0), "+f"(d1), "+f"(d2), "+f"(d3) \
                 : "r"(a0), "r"(a1), "r"(a2), "r"(a3), "r"(b0), "r"(b1))

// ---------------------------------------------------------------------------
// Kernel 1: tf32 tensor-core SGEMM, split-K.
// CTA 64x64 tile, 128 threads = 4 warps (each 32x32), K-chunk 128 in 2 BK=64
// stages. grid (8,8,4) = 256 CTAs. Operands cvt.rna.tf32 during staging.
// A frag LDS banks = lane (stride 68 words); B banks = 8k+n (stride 72) — both
// conflict-free by construction.
// ---------------------------------------------------------------------------
__global__ __launch_bounds__(128)
void gemm_mma_kernel(const float* __restrict__ x, const float* __restrict__ T) {
    __shared__ __align__(16) u32 As[64][68];  // [m][k] tf32 bits, 17 KB
    __shared__ __align__(16) u32 Bs[64][72];  // [k][n] tf32 bits, 18 KB

    const int tid = threadIdx.x;
    const int lane = tid & 31, wid = tid >> 5;
    const int warp_m = (wid >> 1) * 32, warp_n = (wid & 1) * 32;
    const int m0 = blockIdx.y * 64, n0 = blockIdx.x * 64;
    const int koff = blockIdx.z * 128;

    // accumulators: 2 m16-tiles x 4 n8-tiles x 4 f32
    float acc[2][4][4];
#pragma unroll
    for (int mt = 0; mt < 2; mt++)
#pragma unroll
        for (int nt = 0; nt < 4; nt++)
#pragma unroll
            for (int q = 0; q < 4; q++) acc[mt][nt][q] = 0.f;

    // fragment lane addressing (constant per thread)
    const int a_r = lane >> 2, a_c = lane & 3;         // A: row l/4, col l%4
    const int b_k = lane & 3,  b_n = lane >> 2;        // B: k l%4, n l/4

#pragma unroll
    for (int ch = 0; ch < 2; ch++) {
        const int kc = koff + ch * 64;
        // stage A (64 rows x 64 k) and B (64 k x 64 n), f32 -> tf32 bits
#pragma unroll
        for (int it = 0; it < 8; it++) {
            const int idx = tid + 128 * it;         // 0..1023 float4 slots
            const int r = idx >> 4, c4 = (idx & 15) * 4;
            float4 av = *(const float4*)&x[(m0 + r) * FF + kc + c4];
            float4 bv = *(const float4*)&T[(kc + r) * MCOLS + n0 + c4];
            *(uint4*)&As[r][c4] = make_uint4(f2tf32(av.x), f2tf32(av.y),
                                             f2tf32(av.z), f2tf32(av.w));
            *(uint4*)&Bs[r][c4] = make_uint4(f2tf32(bv.x), f2tf32(bv.y),
                                             f2tf32(bv.z), f2tf32(bv.w));
        }
        __syncthreads();

#pragma unroll
        for (int ks = 0; ks < 8; ks++) {
            const int kb = ks * 8;
            u32 a[2][4], b[4][2];
#pragma unroll
            for (int mt = 0; mt < 2; mt++) {
                const int rb = warp_m + mt * 16;
                a[mt][0] = As[rb + a_r][kb + a_c];
                a[mt][1] = As[rb + a_r + 8][kb + a_c];
                a[mt][2] = As[rb + a_r][kb + a_c + 4];
                a[mt][3] = As[rb + a_r + 8][kb + a_c + 4];
            }
#pragma unroll
            for (int nt = 0; nt < 4; nt++) {
                const int nb = warp_n + nt * 8;
                b[nt][0] = Bs[kb + b_k][nb + b_n];
                b[nt][1] = Bs[kb + b_k + 4][nb + b_n];
            }
#pragma unroll
            for (int mt = 0; mt < 2; mt++)
#pragma unroll
                for (int nt = 0; nt < 4; nt++)
                    MMA_TF32(acc[mt][nt][0], acc[mt][nt][1],
                             acc[mt][nt][2], acc[mt][nt][3],
                             a[mt][0], a[mt][1], a[mt][2], a[mt][3],
                             b[nt][0], b[nt][1]);
        }
        __syncthreads();
    }

    // epilogue: C layout r=l/4, c=2*(l%4); rows r and r+8
    float* dst = &g_part[blockIdx.z * (BSZ * MCOLS)];
    const int er = lane >> 2, ec = (lane & 3) * 2;
#pragma unroll
    for (int mt = 0; mt < 2; mt++) {
        const int row0 = m0 + warp_m + mt * 16 + er;
#pragma unroll
        for (int nt = 0; nt < 4; nt++) {
            const int col = n0 + warp_n + nt * 8 + ec;
            *(float2*)&dst[row0 * MCOLS + col] =
                make_float2(acc[mt][nt][0], acc[mt][nt][1]);
            *(float2*)&dst[(row0 + 8) * MCOLS + col] =
                make_float2(acc[mt][nt][2], acc[mt][nt][3]);
        }
    }
}

// ---------------------------------------------------------------------------
// Kernel 2: fused (a) g_negm = -(sum of SPLITK partials)  (b) out[:, :512] = x
// ---------------------------------------------------------------------------
__global__ __launch_bounds__(256)
void reduce_copy_kernel(const float* __restrict__ x, float* __restrict__ out) {
    if (blockIdx.x < 256) {
        const int e = (blockIdx.x * 256 + threadIdx.x) * 4;
        float4 a = make_float4(0.f, 0.f, 0.f, 0.f);
#pragma unroll
        for (int z = 0; z < SPLITK; z++) {
            float4 v = *(const float4*)&g_part[z * (BSZ * MCOLS) + e];
            a.x += v.x; a.y += v.y; a.z += v.z; a.w += v.w;
        }
        *(float4*)&g_negm[e] = make_float4(-a.x, -a.y, -a.z, -a.w);
    } else {
        const int idx = (blockIdx.x - 256) * 256 + threadIdx.x;
        const int i = idx / (FF / 4);
        const int c = idx % (FF / 4);
        *(float4*)&out[i * OUTC + c * 4] = *(const float4*)&x[i * FF + c * 4];
    }
}

// ---------------------------------------------------------------------------
// Kernel 3: feats[i][k] = sum_j exp(-sum_d |m[i,k,d] - m[j,k,d]|)
// grid (16, 32), block 256 = 32 i-lanes x 8 j-splits (64 j each).
// Slice in smem is NEGATED -> diff = packed add; abs via 64-bit AND (alu pipe).
// ---------------------------------------------------------------------------
__global__ __launch_bounds__(256)
void feats_kernel(float* __restrict__ out) {
    const int k  = blockIdx.y;
    const int it = blockIdx.x;
    const int li = threadIdx.x & 31;
    const int js = threadIdx.x >> 5;
    const int i  = it * 32 + li;

    __shared__ __align__(16) float sneg[BSZ * DD];  // 32 KB
    __shared__ float spart[8][32];

    for (int idx = threadIdx.x; idx < BSZ * DD / 4; idx += 256) {
        const int j = idx >> 2;
        const int d4 = (idx & 3) * 4;
        *(float4*)&sneg[j * DD + d4] =
            *(const float4*)&g_negm[j * MCOLS + k * DD + d4];
    }
    __syncthreads();

    u64 mi2[8];
#pragma unroll
    for (int p = 0; p < 4; p++) {
        float4 v = *(const float4*)&g_negm[i * MCOLS + k * DD + p * 4];
        PACK2(mi2[2 * p + 0], -v.x, -v.y);
        PACK2(mi2[2 * p + 1], -v.z, -v.w);
    }

    const u64 ABSM = 0x7FFFFFFF7FFFFFFFull;
    float acc = 0.f;
    const int j0 = js * 64;
#pragma unroll 2
    for (int j = j0; j < j0 + 64; j++) {
        const ulonglong2* row = (const ulonglong2*)&sneg[j * DD];
        u64 s0 = 0ull, s1 = 0ull;
#pragma unroll
        for (int p = 0; p < 4; p++) {
            ulonglong2 rp = row[p];
            u64 d0, d1;
            ADD2(d0, mi2[2 * p], rp.x);
            ADD2(d1, mi2[2 * p + 1], rp.y);
            d0 &= ABSM;
            d1 &= ABSM;
            ADD2(s0, s0, d0);
            ADD2(s1, s1, d1);
        }
        ADD2(s0, s0, s1);
        float lo, hi;
        UNPACK2(lo, hi, s0);
        acc += __expf(-(lo + hi));
    }

    spart[js][li] = acc;
    __syncthreads();
    if (threadIdx.x < 32) {
        float s = 0.f;
#pragma unroll
        for (int q = 0; q < 8; q++) s += spart[q][threadIdx.x];
        out[(it * 32 + threadIdx.x) * OUTC + FF + k] = s;
    }
}

// ---------------------------------------------------------------------------
extern "C" void kernel_launch(void* const* d_in, const int* in_sizes, int n_in,
                              void* d_out, int out_size) {
    const float* x = (const float*)d_in[0];
    const float* T = (const float*)d_in[1];
    float* out = (float*)d_out;

    dim3 ggrd(8, 8, SPLITK);
    gemm_mma_kernel<<<ggrd, 128>>>(x, T);

    reduce_copy_kernel<<<512, 256>>>(x, out);

    dim3 fgrd(16, KK);
    feats_kernel<<<fgrd, 256>>>(out);
}

// round 14
// speedup vs baseline: 2.1863x; 1.0645x over previous
#include <cuda_runtime.h>
#include <cstdint>

#define BSZ 512
#define FF  512
#define KK  32
#define DD  16
#define MCOLS 512
#define OUTC  544

typedef unsigned long long u64;
typedef unsigned int u32;

// reduced negated m (1 MB), L2-resident
__device__ float g_negm[BSZ * MCOLS];

// ---------------- packed f32x2 helpers (for feats) ----------------
#define ADD2(d, a, b)    asm("add.rn.f32x2 %0, %1, %2;" : "=l"(d) : "l"(a), "l"(b))
#define PACK2(d, lo, hi) asm("mov.b64 %0, {%1, %2};"  : "=l"(d) : "f"(lo), "f"(hi))
#define UNPACK2(lo, hi, s) asm("mov.b64 {%0, %1}, %2;" : "=f"(lo), "=f"(hi) : "l"(s))

// ---------------- tf32 mma + cp.async helpers ----------------
#define MMA_TF32(d0, d1, d2, d3, a0, a1, a2, a3, b0, b1) \
    asm volatile("mma.sync.aligned.m16n8k8.row.col.f32.tf32.tf32.f32 " \
                 "{%0,%1,%2,%3}, {%4,%5,%6,%7}, {%8,%9}, {%0,%1,%2,%3};" \
                 : "+f"(d0), "+f"(d1), "+f"(d2), "+f"(d3) \
                 : "r"(a0), "r"(a1), "r"(a2), "r"(a3), "r"(b0), "r"(b1))
#define CPASYNC16(dst, src) \
    asm volatile("cp.async.cg.shared.global [%0], [%1], 16;" :: "r"(dst), "l"(src))
#define CPCOMMIT() asm volatile("cp.async.commit_group;" ::: "memory")
#define CPWAIT0()  asm volatile("cp.async.wait_group 0;" ::: "memory")
#define CPWAIT1()  asm volatile("cp.async.wait_group 1;" ::: "memory")

__device__ __forceinline__ u32 smem_u32(const void* p) {
    u32 a;
    asm("{ .reg .u64 t; cvta.to.shared.u64 t, %1; cvt.u32.u64 %0, t; }" : "=r"(a) : "l"(p));
    return a;
}

// ---------------------------------------------------------------------------
// Kernel 1 (z=0): direct-K tf32 GEMM, 32x64 tile, K=512 in 8 BK=64 chunks,
// cp.async 2-stage double buffer. 128 threads = 4 warps (2m x 2n), each warp
// 16m x 32n. Writes NEGATED m to g_negm.
// Kernel 1 (z=1): out[:, :512] = x  (128 copy CTAs, 4 float4/thread).
// grid (16, 8, 2), block 128.
// ---------------------------------------------------------------------------
__global__ __launch_bounds__(128)
void gemm_fused_kernel(const float* __restrict__ x, const float* __restrict__ T,
                       float* __restrict__ out) {
    if (blockIdx.z == 1) {
        // ---- copy role: 65536 float4 total = 128 CTAs x 128 thr x 4 ----
        const int cid = blockIdx.y * 16 + blockIdx.x;
        const int base = cid * 512;
#pragma unroll
        for (int s = 0; s < 4; s++) {
            const int q = base + s * 128 + threadIdx.x;   // float4 index, < 65536
            const int i = q >> 7, c = q & 127;
            *(float4*)&out[i * OUTC + c * 4] = *(const float4*)&x[i * FF + c * 4];
        }
        return;
    }

    // ---- GEMM role ----
    __shared__ __align__(16) float As[2][32][68];  // [buf][m][k]
    __shared__ __align__(16) float Bs[2][64][72];  // [buf][k][n]

    const int tid = threadIdx.x;
    const int lane = tid & 31, wid = tid >> 5;
    const int rb = (wid >> 1) * 16;          // warp m-base (within 32)
    const int wn = (wid & 1) * 32;           // warp n-base (within 64)
    const int m0 = blockIdx.x * 32, n0 = blockIdx.y * 64;

    const u32 asb = smem_u32(As), bsb = smem_u32(Bs);

    // A chunk = 32 rows x 64 f32 = 512 granules (4/thread)
    // B chunk = 64 rows x 64 f32 = 1024 granules (8/thread)
    auto stage = [&](int buf, int kc) {
#pragma unroll
        for (int s = 0; s < 4; s++) {
            const int idx = tid + 128 * s;               // 0..511
            const int r = idx >> 4, c4 = (idx & 15) * 4;
            CPASYNC16(asb + ((buf * 32 + r) * 68 + c4) * 4,
                      &x[(m0 + r) * FF + kc + c4]);
        }
#pragma unroll
        for (int s = 0; s < 8; s++) {
            const int idx = tid + 128 * s;               // 0..1023
            const int r = idx >> 4, c4 = (idx & 15) * 4;
            CPASYNC16(bsb + ((buf * 64 + r) * 72 + c4) * 4,
                      &T[(kc + r) * MCOLS + n0 + c4]);
        }
        CPCOMMIT();
    };

    // fragment lane addressing
    const int fa_r = lane >> 2, fa_c = lane & 3;   // A: row l/4, col l%4
    const int fb_k = lane & 3,  fb_n = lane >> 2;  // B: k l%4, n l/4

    float acc[4][4];
#pragma unroll
    for (int nt = 0; nt < 4; nt++)
#pragma unroll
        for (int q = 0; q < 4; q++) acc[nt][q] = 0.f;

    stage(0, 0);

#pragma unroll
    for (int ch = 0; ch < 8; ch++) {
        const int buf = ch & 1;
        const bool pre = (ch + 1) < 8;
        if (pre) stage(buf ^ 1, (ch + 1) * 64);
        if (pre) CPWAIT1(); else CPWAIT0();
        __syncthreads();

#pragma unroll
        for (int ks = 0; ks < 8; ks++) {
            const int kb = ks * 8;
            u32 a0 = __float_as_uint(As[buf][rb + fa_r][kb + fa_c]);
            u32 a1 = __float_as_uint(As[buf][rb + fa_r + 8][kb + fa_c]);
            u32 a2 = __float_as_uint(As[buf][rb + fa_r][kb + fa_c + 4]);
            u32 a3 = __float_as_uint(As[buf][rb + fa_r + 8][kb + fa_c + 4]);
#pragma unroll
            for (int nt = 0; nt < 4; nt++) {
                const int nb = wn + nt * 8;
                u32 b0 = __float_as_uint(Bs[buf][kb + fb_k][nb + fb_n]);
                u32 b1 = __float_as_uint(Bs[buf][kb + fb_k + 4][nb + fb_n]);
                MMA_TF32(acc[nt][0], acc[nt][1], acc[nt][2], acc[nt][3],
                         a0, a1, a2, a3, b0, b1);
            }
        }
        __syncthreads();   // all warps done with buf before it is re-staged
    }

    // epilogue: write NEGATED. C frag: row = l/4 (+8), col = 2*(l%4)
    const int er = lane >> 2, ec = (lane & 3) * 2;
#pragma unroll
    for (int nt = 0; nt < 4; nt++) {
        const int col = n0 + wn + nt * 8 + ec;
        const int row0 = m0 + rb + er;
        *(float2*)&g_negm[row0 * MCOLS + col] =
            make_float2(-acc[nt][0], -acc[nt][1]);
        *(float2*)&g_negm[(row0 + 8) * MCOLS + col] =
            make_float2(-acc[nt][2], -acc[nt][3]);
    }
}

// ---------------------------------------------------------------------------
// Kernel 2: feats[i][k] = sum_j exp(-sum_d |m[i,k,d] - m[j,k,d]|)
// grid (16, 32), block 256 = 32 i-lanes x 8 j-splits (64 j each).
// Slice in smem is NEGATED -> diff = packed add; abs via 64-bit AND (alu pipe).
// ---------------------------------------------------------------------------
__global__ __launch_bounds__(256)
void feats_kernel(float* __restrict__ out) {
    const int k  = blockIdx.y;
    const int it = blockIdx.x;
    const int li = threadIdx.x & 31;
    const int js = threadIdx.x >> 5;
    const int i  = it * 32 + li;

    __shared__ __align__(16) float sneg[BSZ * DD];  // 32 KB
    __shared__ float spart[8][32];

    for (int idx = threadIdx.x; idx < BSZ * DD / 4; idx += 256) {
        const int j = idx >> 2;
        const int d4 = (idx & 3) * 4;
        *(float4*)&sneg[j * DD + d4] =
            *(const float4*)&g_negm[j * MCOLS + k * DD + d4];
    }
    __syncthreads();

    u64 mi2[8];
#pragma unroll
    for (int p = 0; p < 4; p++) {
        float4 v = *(const float4*)&g_negm[i * MCOLS + k * DD + p * 4];
        PACK2(mi2[2 * p + 0], -v.x, -v.y);
        PACK2(mi2[2 * p + 1], -v.z, -v.w);
    }

    const u64 ABSM = 0x7FFFFFFF7FFFFFFFull;
    float acc = 0.f;
    const int j0 = js * 64;
#pragma unroll 2
    for (int j = j0; j < j0 + 64; j++) {
        const ulonglong2* row = (const ulonglong2*)&sneg[j * DD];
        u64 s0 = 0ull, s1 = 0ull;
#pragma unroll
        for (int p = 0; p < 4; p++) {
            ulonglong2 rp = row[p];
            u64 d0, d1;
            ADD2(d0, mi2[2 * p], rp.x);
            ADD2(d1, mi2[2 * p + 1], rp.y);
            d0 &= ABSM;
            d1 &= ABSM;
            ADD2(s0, s0, d0);
            ADD2(s1, s1, d1);
        }
        ADD2(s0, s0, s1);
        float lo, hi;
        UNPACK2(lo, hi, s0);
        acc += __expf(-(lo + hi));
    }

    spart[js][li] = acc;
    __syncthreads();
    if (threadIdx.x < 32) {
        float s = 0.f;
#pragma unroll
        for (int q = 0; q < 8; q++) s += spart[q][threadIdx.x];
        out[(it * 32 + threadIdx.x) * OUTC + FF + k] = s;
    }
}

// ---------------------------------------------------------------------------
extern "C" void kernel_launch(void* const* d_in, const int* in_sizes, int n_in,
                              void* d_out, int out_size) {
    const float* x = (const float*)d_in[0];
    const float* T = (const float*)d_in[1];
    float* out = (float*)d_out;

    dim3 ggrd(16, 8, 2);
    gemm_fused_kernel<<<ggrd, 128>>>(x, T, out);

    dim3 fgrd(16, KK);
    feats_kernel<<<fgrd, 256>>>(out);
}

// round 16
// speedup vs baseline: 2.3268x; 1.0643x over previous
#include <cuda_runtime.h>
#include <cstdint>

#define BSZ 512
#define FF  512
#define KK  32
#define DD  16
#define MCOLS 512
#define OUTC  544

typedef unsigned long long u64;
typedef unsigned int u32;

// reduced negated m (1 MB), L2-resident
__device__ float g_negm[BSZ * MCOLS];

// ---------------- packed f32x2 helpers (for feats) ----------------
#define ADD2(d, a, b)    asm("add.rn.f32x2 %0, %1, %2;" : "=l"(d) : "l"(a), "l"(b))
#define PACK2(d, lo, hi) asm("mov.b64 %0, {%1, %2};"  : "=l"(d) : "f"(lo), "f"(hi))
#define UNPACK2(lo, hi, s) asm("mov.b64 {%0, %1}, %2;" : "=f"(lo), "=f"(hi) : "l"(s))

// ---------------- tf32 mma + cp.async helpers ----------------
#define MMA_TF32(d0, d1, d2, d3, a0, a1, a2, a3, b0, b1) \
    asm volatile("mma.sync.aligned.m16n8k8.row.col.f32.tf32.tf32.f32 " \
                 "{%0,%1,%2,%3}, {%4,%5,%6,%7}, {%8,%9}, {%0,%1,%2,%3};" \
                 : "+f"(d0), "+f"(d1), "+f"(d2), "+f"(d3) \
                 : "r"(a0), "r"(a1), "r"(a2), "r"(a3), "r"(b0), "r"(b1))
#define CPASYNC16(dst, src) \
    asm volatile("cp.async.cg.shared.global [%0], [%1], 16;" :: "r"(dst), "l"(src))
#define CPCOMMIT() asm volatile("cp.async.commit_group;" ::: "memory")
#define CPWAIT0()  asm volatile("cp.async.wait_group 0;" ::: "memory")
#define CPWAIT1()  asm volatile("cp.async.wait_group 1;" ::: "memory")

__device__ __forceinline__ u32 smem_u32(const void* p) {
    u32 a;
    asm("{ .reg .u64 t; cvta.to.shared.u64 t, %1; cvt.u32.u64 %0, t; }" : "=r"(a) : "l"(p));
    return a;
}

// ---------------------------------------------------------------------------
// Kernel 1 (z=0): direct-K tf32 GEMM, 32x64 tile, K=512 in 8 BK=64 chunks,
// cp.async 2-stage double buffer. Writes NEGATED m to g_negm.
// Kernel 1 (z=1): out[:, :512] = x  (copy, 4 float4/thread).
// grid (16, 8, 2), block 128.
// ---------------------------------------------------------------------------
__global__ __launch_bounds__(128)
void gemm_fused_kernel(const float* __restrict__ x, const float* __restrict__ T,
                       float* __restrict__ out) {
    if (blockIdx.z == 1) {
        // ---- copy role: 65536 float4 total = 128 CTAs x 128 thr x 4 ----
        const int cid = blockIdx.y * 16 + blockIdx.x;
        const int base = cid * 512;
#pragma unroll
        for (int s = 0; s < 4; s++) {
            const int q = base + s * 128 + threadIdx.x;   // float4 index, < 65536
            const int i = q >> 7, c = q & 127;
            *(float4*)&out[i * OUTC + c * 4] = *(const float4*)&x[i * FF + c * 4];
        }
        return;
    }

    // ---- GEMM role ----
    __shared__ __align__(16) float As[2][32][68];  // [buf][m][k]
    __shared__ __align__(16) float Bs[2][64][72];  // [buf][k][n]

    const int tid = threadIdx.x;
    const int lane = tid & 31, wid = tid >> 5;
    const int rb = (wid >> 1) * 16;          // warp m-base (within 32)
    const int wn = (wid & 1) * 32;           // warp n-base (within 64)
    const int m0 = blockIdx.x * 32, n0 = blockIdx.y * 64;

    const u32 asb = smem_u32(As), bsb = smem_u32(Bs);

    auto stage = [&](int buf, int kc) {
#pragma unroll
        for (int s = 0; s < 4; s++) {
            const int idx = tid + 128 * s;               // 0..511
            const int r = idx >> 4, c4 = (idx & 15) * 4;
            CPASYNC16(asb + ((buf * 32 + r) * 68 + c4) * 4,
                      &x[(m0 + r) * FF + kc + c4]);
        }
#pragma unroll
        for (int s = 0; s < 8; s++) {
            const int idx = tid + 128 * s;               // 0..1023
            const int r = idx >> 4, c4 = (idx & 15) * 4;
            CPASYNC16(bsb + ((buf * 64 + r) * 72 + c4) * 4,
                      &T[(kc + r) * MCOLS + n0 + c4]);
        }
        CPCOMMIT();
    };

    const int fa_r = lane >> 2, fa_c = lane & 3;   // A: row l/4, col l%4
    const int fb_k = lane & 3,  fb_n = lane >> 2;  // B: k l%4, n l/4

    float acc[4][4];
#pragma unroll
    for (int nt = 0; nt < 4; nt++)
#pragma unroll
        for (int q = 0; q < 4; q++) acc[nt][q] = 0.f;

    stage(0, 0);

#pragma unroll
    for (int ch = 0; ch < 8; ch++) {
        const int buf = ch & 1;
        const bool pre = (ch + 1) < 8;
        if (pre) stage(buf ^ 1, (ch + 1) * 64);
        if (pre) CPWAIT1(); else CPWAIT0();
        __syncthreads();

#pragma unroll
        for (int ks = 0; ks < 8; ks++) {
            const int kb = ks * 8;
            u32 a0 = __float_as_uint(As[buf][rb + fa_r][kb + fa_c]);
            u32 a1 = __float_as_uint(As[buf][rb + fa_r + 8][kb + fa_c]);
            u32 a2 = __float_as_uint(As[buf][rb + fa_r][kb + fa_c + 4]);
            u32 a3 = __float_as_uint(As[buf][rb + fa_r + 8][kb + fa_c + 4]);
#pragma unroll
            for (int nt = 0; nt < 4; nt++) {
                const int nb = wn + nt * 8;
                u32 b0 = __float_as_uint(Bs[buf][kb + fb_k][nb + fb_n]);
                u32 b1 = __float_as_uint(Bs[buf][kb + fb_k + 4][nb + fb_n]);
                MMA_TF32(acc[nt][0], acc[nt][1], acc[nt][2], acc[nt][3],
                         a0, a1, a2, a3, b0, b1);
            }
        }
        __syncthreads();
    }

    // epilogue: write NEGATED. C frag: row = l/4 (+8), col = 2*(l%4)
    const int er = lane >> 2, ec = (lane & 3) * 2;
#pragma unroll
    for (int nt = 0; nt < 4; nt++) {
        const int col = n0 + wn + nt * 8 + ec;
        const int row0 = m0 + rb + er;
        *(float2*)&g_negm[row0 * MCOLS + col] =
            make_float2(-acc[nt][0], -acc[nt][1]);
        *(float2*)&g_negm[(row0 + 8) * MCOLS + col] =
            make_float2(-acc[nt][2], -acc[nt][3]);
    }
}

// ---------------------------------------------------------------------------
// Kernel 2: feats[i][k] = sum_j exp(-sum_d |m[i,k,d] - m[j,k,d]|)
// grid (8, 32) = 256 CTAs, block 256 = 32 i-lanes x 8 j-splits (64 j each).
// Each thread handles TWO i-rows (i0 = blk*64+li, i1 = i0+32): two fully
// independent dependency chains per j-step + amortized LDS -> high ILP.
// Slice in smem is NEGATED -> diff = packed add; abs via 64-bit AND (alu pipe).
// ---------------------------------------------------------------------------
__global__ __launch_bounds__(256)
void feats_kernel(float* __restrict__ out) {
    const int k  = blockIdx.y;
    const int ib = blockIdx.x;                 // 8 i-blocks of 64
    const int li = threadIdx.x & 31;
    const int js = threadIdx.x >> 5;           // 8 j-splits of 64
    const int i0 = ib * 64 + li;
    const int i1 = i0 + 32;

    __shared__ __align__(16) float sneg[BSZ * DD];  // 32 KB
    __shared__ float spart[8][64];

#pragma unroll
    for (int s = 0; s < 8; s++) {
        const int idx = threadIdx.x + 256 * s;     // 0..2047 float4 slots
        const int j = idx >> 2;
        const int d4 = (idx & 3) * 4;
        *(float4*)&sneg[j * DD + d4] =
            *(const float4*)&g_negm[j * MCOLS + k * DD + d4];
    }
    __syncthreads();

    // two i-rows in registers (positive values)
    u64 mi0[8], mi1[8];
#pragma unroll
    for (int p = 0; p < 4; p++) {
        float4 v0 = *(const float4*)&g_negm[i0 * MCOLS + k * DD + p * 4];
        float4 v1 = *(const float4*)&g_negm[i1 * MCOLS + k * DD + p * 4];
        PACK2(mi0[2 * p + 0], -v0.x, -v0.y);
        PACK2(mi0[2 * p + 1], -v0.z, -v0.w);
        PACK2(mi1[2 * p + 0], -v1.x, -v1.y);
        PACK2(mi1[2 * p + 1], -v1.z, -v1.w);
    }

    const u64 ABSM = 0x7FFFFFFF7FFFFFFFull;
    float acc0 = 0.f, acc1 = 0.f;
    const int j0 = js * 64;
#pragma unroll 2
    for (int j = j0; j < j0 + 64; j++) {
        const ulonglong2* row = (const ulonglong2*)&sneg[j * DD];
        ulonglong2 rpa = row[0], rpb = row[1], rpc = row[2], rpd = row[3];
        u64 a0 = 0ull, a1 = 0ull, b0 = 0ull, b1 = 0ull;
        u64 d;
        // chain A (i0)
        ADD2(d, mi0[0], rpa.x); d &= ABSM; ADD2(a0, a0, d);
        ADD2(d, mi0[1], rpa.y); d &= ABSM; ADD2(a1, a1, d);
        ADD2(d, mi0[2], rpb.x); d &= ABSM; ADD2(a0, a0, d);
        ADD2(d, mi0[3], rpb.y); d &= ABSM; ADD2(a1, a1, d);
        ADD2(d, mi0[4], rpc.x); d &= ABSM; ADD2(a0, a0, d);
        ADD2(d, mi0[5], rpc.y); d &= ABSM; ADD2(a1, a1, d);
        ADD2(d, mi0[6], rpd.x); d &= ABSM; ADD2(a0, a0, d);
        ADD2(d, mi0[7], rpd.y); d &= ABSM; ADD2(a1, a1, d);
        // chain B (i1) — independent
        u64 e;
        ADD2(e, mi1[0], rpa.x); e &= ABSM; ADD2(b0, b0, e);
        ADD2(e, mi1[1], rpa.y); e &= ABSM; ADD2(b1, b1, e);
        ADD2(e, mi1[2], rpb.x); e &= ABSM; ADD2(b0, b0, e);
        ADD2(e, mi1[3], rpb.y); e &= ABSM; ADD2(b1, b1, e);
        ADD2(e, mi1[4], rpc.x); e &= ABSM; ADD2(b0, b0, e);
        ADD2(e, mi1[5], rpc.y); e &= ABSM; ADD2(b1, b1, e);
        ADD2(e, mi1[6], rpd.x); e &= ABSM; ADD2(b0, b0, e);
        ADD2(e, mi1[7], rpd.y); e &= ABSM; ADD2(b1, b1, e);

        ADD2(a0, a0, a1);
        ADD2(b0, b0, b1);
        float lo0, hi0, lo1, hi1;
        UNPACK2(lo0, hi0, a0);
        UNPACK2(lo1, hi1, b0);
        acc0 += __expf(-(lo0 + hi0));
        acc1 += __expf(-(lo1 + hi1));
    }

    spart[js][li] = acc0;
    spart[js][li + 32] = acc1;
    __syncthreads();
    if (threadIdx.x < 64) {
        float s = 0.f;
#pragma unroll
        for (int q = 0; q < 8; q++) s += spart[q][threadIdx.x];
        out[(ib * 64 + threadIdx.x) * OUTC + FF + k] = s;
    }
}

// ---------------------------------------------------------------------------
extern "C" void kernel_launch(void* const* d_in, const int* in_sizes, int n_in,
                              void* d_out, int out_size) {
    const float* x = (const float*)d_in[0];
    const float* T = (const float*)d_in[1];
    float* out = (float*)d_out;

    dim3 ggrd(16, 8, 2);
    gemm_fused_kernel<<<ggrd, 128>>>(x, T, out);

    dim3 fgrd(8, KK);
    feats_kernel<<<fgrd, 256>>>(out);
}

// round 17
// speedup vs baseline: 2.3447x; 1.0077x over previous
#include <cuda_runtime.h>
#include <cstdint>

#define BSZ 512
#define FF  512
#define KK  32
#define DD  16
#define MCOLS 512
#define OUTC  544

typedef unsigned long long u64;
typedef unsigned int u32;

// reduced negated m (1 MB), L2-resident
__device__ float g_negm[BSZ * MCOLS];

// ---------------- packed f32x2 helpers (for feats) ----------------
#define ADD2(d, a, b)    asm("add.rn.f32x2 %0, %1, %2;" : "=l"(d) : "l"(a), "l"(b))
#define PACK2(d, lo, hi) asm("mov.b64 %0, {%1, %2};"  : "=l"(d) : "f"(lo), "f"(hi))
#define UNPACK2(lo, hi, s) asm("mov.b64 {%0, %1}, %2;" : "=f"(lo), "=f"(hi) : "l"(s))

// ---------------- tf32 mma + cp.async helpers ----------------
#define MMA_TF32(d0, d1, d2, d3, a0, a1, a2, a3, b0, b1) \
    asm volatile("mma.sync.aligned.m16n8k8.row.col.f32.tf32.tf32.f32 " \
                 "{%0,%1,%2,%3}, {%4,%5,%6,%7}, {%8,%9}, {%0,%1,%2,%3};" \
                 : "+f"(d0), "+f"(d1), "+f"(d2), "+f"(d3) \
                 : "r"(a0), "r"(a1), "r"(a2), "r"(a3), "r"(b0), "r"(b1))
#define CPASYNC16(dst, src) \
    asm volatile("cp.async.cg.shared.global [%0], [%1], 16;" :: "r"(dst), "l"(src))
#define CPCOMMIT() asm volatile("cp.async.commit_group;" ::: "memory")
#define CPWAIT0()  asm volatile("cp.async.wait_group 0;" ::: "memory")
#define CPWAIT1()  asm volatile("cp.async.wait_group 1;" ::: "memory")

__device__ __forceinline__ u32 smem_u32(const void* p) {
    u32 a;
    asm("{ .reg .u64 t; cvta.to.shared.u64 t, %1; cvt.u32.u64 %0, t; }" : "=r"(a) : "l"(p));
    return a;
}

// ---------------------------------------------------------------------------
// Kernel 1 (z=0): direct-K tf32 GEMM, 32x64 tile, K=512 in 8 BK=64 chunks,
// cp.async 2-stage double buffer. Writes NEGATED m to g_negm.
// Kernel 1 (z=1): out[:, :512] = x  (copy, 4 float4/thread).
// grid (16, 8, 2), block 128.
// ---------------------------------------------------------------------------
__global__ __launch_bounds__(128)
void gemm_fused_kernel(const float* __restrict__ x, const float* __restrict__ T,
                       float* __restrict__ out) {
    if (blockIdx.z == 1) {
        const int cid = blockIdx.y * 16 + blockIdx.x;
        const int base = cid * 512;
#pragma unroll
        for (int s = 0; s < 4; s++) {
            const int q = base + s * 128 + threadIdx.x;   // float4 index, < 65536
            const int i = q >> 7, c = q & 127;
            *(float4*)&out[i * OUTC + c * 4] = *(const float4*)&x[i * FF + c * 4];
        }
        return;
    }

    // ---- GEMM role ----
    __shared__ __align__(16) float As[2][32][68];  // [buf][m][k]
    __shared__ __align__(16) float Bs[2][64][72];  // [buf][k][n]

    const int tid = threadIdx.x;
    const int lane = tid & 31, wid = tid >> 5;
    const int rb = (wid >> 1) * 16;
    const int wn = (wid & 1) * 32;
    const int m0 = blockIdx.x * 32, n0 = blockIdx.y * 64;

    const u32 asb = smem_u32(As), bsb = smem_u32(Bs);

    auto stage = [&](int buf, int kc) {
#pragma unroll
        for (int s = 0; s < 4; s++) {
            const int idx = tid + 128 * s;
            const int r = idx >> 4, c4 = (idx & 15) * 4;
            CPASYNC16(asb + ((buf * 32 + r) * 68 + c4) * 4,
                      &x[(m0 + r) * FF + kc + c4]);
        }
#pragma unroll
        for (int s = 0; s < 8; s++) {
            const int idx = tid + 128 * s;
            const int r = idx >> 4, c4 = (idx & 15) * 4;
            CPASYNC16(bsb + ((buf * 64 + r) * 72 + c4) * 4,
                      &T[(kc + r) * MCOLS + n0 + c4]);
        }
        CPCOMMIT();
    };

    const int fa_r = lane >> 2, fa_c = lane & 3;
    const int fb_k = lane & 3,  fb_n = lane >> 2;

    float acc[4][4];
#pragma unroll
    for (int nt = 0; nt < 4; nt++)
#pragma unroll
        for (int q = 0; q < 4; q++) acc[nt][q] = 0.f;

    stage(0, 0);

#pragma unroll
    for (int ch = 0; ch < 8; ch++) {
        const int buf = ch & 1;
        const bool pre = (ch + 1) < 8;
        if (pre) stage(buf ^ 1, (ch + 1) * 64);
        if (pre) CPWAIT1(); else CPWAIT0();
        __syncthreads();

#pragma unroll
        for (int ks = 0; ks < 8; ks++) {
            const int kb = ks * 8;
            u32 a0 = __float_as_uint(As[buf][rb + fa_r][kb + fa_c]);
            u32 a1 = __float_as_uint(As[buf][rb + fa_r + 8][kb + fa_c]);
            u32 a2 = __float_as_uint(As[buf][rb + fa_r][kb + fa_c + 4]);
            u32 a3 = __float_as_uint(As[buf][rb + fa_r + 8][kb + fa_c + 4]);
#pragma unroll
            for (int nt = 0; nt < 4; nt++) {
                const int nb = wn + nt * 8;
                u32 b0 = __float_as_uint(Bs[buf][kb + fb_k][nb + fb_n]);
                u32 b1 = __float_as_uint(Bs[buf][kb + fb_k + 4][nb + fb_n]);
                MMA_TF32(acc[nt][0], acc[nt][1], acc[nt][2], acc[nt][3],
                         a0, a1, a2, a3, b0, b1);
            }
        }
        __syncthreads();
    }

    const int er = lane >> 2, ec = (lane & 3) * 2;
#pragma unroll
    for (int nt = 0; nt < 4; nt++) {
        const int col = n0 + wn + nt * 8 + ec;
        const int row0 = m0 + rb + er;
        *(float2*)&g_negm[row0 * MCOLS + col] =
            make_float2(-acc[nt][0], -acc[nt][1]);
        *(float2*)&g_negm[(row0 + 8) * MCOLS + col] =
            make_float2(-acc[nt][2], -acc[nt][3]);
    }
}

// ---------------------------------------------------------------------------
// Kernel 2: feats[i][k] = sum_j exp(-sum_d |m[i,k,d] - m[j,k,d]|)
// grid (8, 32) = 256 CTAs, block 512 = 32 i-lanes x 16 j-splits (32 j each).
// 16 warps/CTA -> ~28 resident warps/SM (occ ~43%) for latency hiding.
// Each thread: TWO i-rows (i0, i0+32) -> 4+ independent chains per j-step.
// Slice in smem NEGATED -> diff = packed add; abs via 64-bit AND (alu pipe).
// ---------------------------------------------------------------------------
__global__ __launch_bounds__(512)
void feats_kernel(float* __restrict__ out) {
    const int k  = blockIdx.y;
    const int ib = blockIdx.x;                 // 8 i-blocks of 64
    const int li = threadIdx.x & 31;
    const int js = threadIdx.x >> 5;           // 16 j-splits of 32
    const int i0 = ib * 64 + li;
    const int i1 = i0 + 32;

    __shared__ __align__(16) float sneg[BSZ * DD];  // 32 KB
    __shared__ float spart[16][64];                 // 4 KB

#pragma unroll
    for (int s = 0; s < 4; s++) {
        const int idx = threadIdx.x + 512 * s;     // 0..2047 float4 slots
        const int j = idx >> 2;
        const int d4 = (idx & 3) * 4;
        *(float4*)&sneg[j * DD + d4] =
            *(const float4*)&g_negm[j * MCOLS + k * DD + d4];
    }
    __syncthreads();

    // two i-rows in registers (positive values)
    u64 mi0[8], mi1[8];
#pragma unroll
    for (int p = 0; p < 4; p++) {
        float4 v0 = *(const float4*)&g_negm[i0 * MCOLS + k * DD + p * 4];
        float4 v1 = *(const float4*)&g_negm[i1 * MCOLS + k * DD + p * 4];
        PACK2(mi0[2 * p + 0], -v0.x, -v0.y);
        PACK2(mi0[2 * p + 1], -v0.z, -v0.w);
        PACK2(mi1[2 * p + 0], -v1.x, -v1.y);
        PACK2(mi1[2 * p + 1], -v1.z, -v1.w);
    }

    const u64 ABSM = 0x7FFFFFFF7FFFFFFFull;
    float acc0 = 0.f, acc1 = 0.f;
    const int j0 = js * 32;
#pragma unroll 2
    for (int j = j0; j < j0 + 32; j++) {
        const ulonglong2* row = (const ulonglong2*)&sneg[j * DD];
        ulonglong2 rpa = row[0], rpb = row[1], rpc = row[2], rpd = row[3];
        u64 a0 = 0ull, a1 = 0ull, b0 = 0ull, b1 = 0ull;
        u64 d;
        // chain A (i0)
        ADD2(d, mi0[0], rpa.x); d &= ABSM; ADD2(a0, a0, d);
        ADD2(d, mi0[1], rpa.y); d &= ABSM; ADD2(a1, a1, d);
        ADD2(d, mi0[2], rpb.x); d &= ABSM; ADD2(a0, a0, d);
        ADD2(d, mi0[3], rpb.y); d &= ABSM; ADD2(a1, a1, d);
        ADD2(d, mi0[4], rpc.x); d &= ABSM; ADD2(a0, a0, d);
        ADD2(d, mi0[5], rpc.y); d &= ABSM; ADD2(a1, a1, d);
        ADD2(d, mi0[6], rpd.x); d &= ABSM; ADD2(a0, a0, d);
        ADD2(d, mi0[7], rpd.y); d &= ABSM; ADD2(a1, a1, d);
        // chain B (i1) — independent
        u64 e;
        ADD2(e, mi1[0], rpa.x); e &= ABSM; ADD2(b0, b0, e);
        ADD2(e, mi1[1], rpa.y); e &= ABSM; ADD2(b1, b1, e);
        ADD2(e, mi1[2], rpb.x); e &= ABSM; ADD2(b0, b0, e);
        ADD2(e, mi1[3], rpb.y); e &= ABSM; ADD2(b1, b1, e);
        ADD2(e, mi1[4], rpc.x); e &= ABSM; ADD2(b0, b0, e);
        ADD2(e, mi1[5], rpc.y); e &= ABSM; ADD2(b1, b1, e);
        ADD2(e, mi1[6], rpd.x); e &= ABSM; ADD2(b0, b0, e);
        ADD2(e, mi1[7], rpd.y); e &= ABSM; ADD2(b1, b1, e);

        ADD2(a0, a0, a1);
        ADD2(b0, b0, b1);
        float lo0, hi0, lo1, hi1;
        UNPACK2(lo0, hi0, a0);
        UNPACK2(lo1, hi1, b0);
        acc0 += __expf(-(lo0 + hi0));
        acc1 += __expf(-(lo1 + hi1));
    }

    spart[js][li] = acc0;
    spart[js][li + 32] = acc1;
    __syncthreads();
    if (threadIdx.x < 64) {
        float s = 0.f;
#pragma unroll
        for (int q = 0; q < 16; q++) s += spart[q][threadIdx.x];
        out[(ib * 64 + threadIdx.x) * OUTC + FF + k] = s;
    }
}

// ---------------------------------------------------------------------------
extern "C" void kernel_launch(void* const* d_in, const int* in_sizes, int n_in,
                              void* d_out, int out_size) {
    const float* x = (const float*)d_in[0];
    const float* T = (const float*)d_in[1];
    float* out = (float*)d_out;

    dim3 ggrd(16, 8, 2);
    gemm_fused_kernel<<<ggrd, 128>>>(x, T, out);

    dim3 fgrd(8, KK);
    feats_kernel<<<fgrd, 512>>>(out);
}